// round 10
// baseline (speedup 1.0000x reference)
#include <cuda_runtime.h>
#include <cuda_bf16.h>
#include <math.h>

// Problem constants
#define NN      50000      // nodes
#define EE      800000     // edges (before self loops)
#define ET      850000     // edges + self loops
#define FIN     64
#define HH      128
#define GG      512
#define NEG     0.2f

#define NB_SCAN 196        // ceil(NN/256)

// ---------------- scratch (device globals; referenced by symbol only) ---------
__device__ __align__(256) float g_xl[NN * HH];
__device__ __align__(256) float g_xr[NN * HH];
__device__ __align__(256) float g_h1[NN * HH];
__device__ int   g_counts[NN];
__device__ int   g_off[NN + 1];
__device__ int   g_cursor[NN];
__device__ int   g_srclist[ET];
__device__ int   g_blockTot[256];
__device__ int   g_blockOff[256];
__device__ float g_sums[GG];
__device__ float g_cnt[GG];

// ---------------- init ----------------
__global__ void init_kernel() {
    int i = blockIdx.x * blockDim.x + threadIdx.x;
    if (i < NN) g_counts[i] = 0;
    if (i < GG) { g_sums[i] = 0.f; g_cnt[i] = 0.f; }
}

// ---------------- CSR build (edge_index/batch are int32) ----------------
__global__ void count_kernel(const int* __restrict__ ei) {
    int i = blockIdx.x * blockDim.x + threadIdx.x;
    if (i >= ET) return;
    int d = (i < EE) ? ei[EE + i] : (i - EE);
    atomicAdd(&g_counts[d], 1);
}

__global__ void scan_block_tot() {
    __shared__ int sm[256];
    int i = blockIdx.x * 256 + threadIdx.x;
    int v = (i < NN) ? g_counts[i] : 0;
    sm[threadIdx.x] = v;
    __syncthreads();
    for (int st = 128; st > 0; st >>= 1) {
        if (threadIdx.x < st) sm[threadIdx.x] += sm[threadIdx.x + st];
        __syncthreads();
    }
    if (threadIdx.x == 0) g_blockTot[blockIdx.x] = sm[0];
}

__global__ void scan_block_off() {
    __shared__ int sm[256];
    int t = threadIdx.x;
    int v = (t < NB_SCAN) ? g_blockTot[t] : 0;
    sm[t] = v;
    __syncthreads();
    for (int st = 1; st < 256; st <<= 1) {
        int a = (t >= st) ? sm[t - st] : 0;
        __syncthreads();
        sm[t] += a;
        __syncthreads();
    }
    if (t < NB_SCAN) g_blockOff[t] = sm[t] - v;   // exclusive
}

__global__ void scan_write_off() {
    __shared__ int sm[256];
    int t = threadIdx.x;
    int i = blockIdx.x * 256 + t;
    int v = (i < NN) ? g_counts[i] : 0;
    sm[t] = v;
    __syncthreads();
    for (int st = 1; st < 256; st <<= 1) {
        int a = (t >= st) ? sm[t - st] : 0;
        __syncthreads();
        sm[t] += a;
        __syncthreads();
    }
    if (i < NN) {
        int ex = g_blockOff[blockIdx.x] + sm[t] - v;
        g_off[i] = ex;
        g_cursor[i] = ex;
    }
    if (i == 0) g_off[NN] = ET;
}

__global__ void fill_kernel(const int* __restrict__ ei) {
    int i = blockIdx.x * blockDim.x + threadIdx.x;
    if (i >= ET) return;
    int s, d;
    if (i < EE) { s = ei[i]; d = ei[EE + i]; }
    else        { s = d = i - EE; }
    int pos = atomicAdd(&g_cursor[d], 1);
    g_srclist[pos] = s;
}

// ---------------- FFMA2 SGEMM pair: {g_xl,g_xr} = X @ W{l,r} + b{l,r} --------
// 128x128 block tile, BK=32, packed fp32x2 math (fma.rn.f32x2 -> FFMA2, 2x
// fp32 rate, exact IEEE fp32 per lane). X staged transposed [k][row] so
// ld.shared.v2.b64 yields packed ROW-pairs; W staged DUPLICATED [k][2c]=[k][2c+1]
// so ld.shared.v2.b64 yields dup-packed W operands. Zero pack instructions.
#define FFMA2(acc, a, b) \
    asm("fma.rn.f32x2 %0, %1, %2, %0;" : "+l"(acc) : "l"(a), "l"(b))

template<int K, bool X_FROM_H1>
__global__ __launch_bounds__(256) void gemm_pair_kernel(
    const float* __restrict__ Xin,
    const float* __restrict__ Wl, const float* __restrict__ bl,
    const float* __restrict__ Wr, const float* __restrict__ br,
    int nrows)
{
    __shared__ float Xs[32][128];   // [k][row] transposed, 16KB
    __shared__ float Wd[32][256];   // [k][dup col], 32KB  (total 48KB exactly)

    const float* X    = X_FROM_H1 ? g_h1 : Xin;
    const float* W    = blockIdx.y ? Wr : Wl;
    const float* bias = blockIdx.y ? br : bl;
    float*       Y    = blockIdx.y ? g_xr : g_xl;

    const int tid = threadIdx.x;
    const int tx = tid & 15;          // col group (8 cols: tx*4.., 64+tx*4..)
    const int ty = tid >> 4;          // row group (8 rows: ty*4.., 64+ty*4..)
    const int row0 = blockIdx.x * 128;

    // packed accumulators: acc2[rp][c]; rp=row-pair (0,1: rows ty*4+{0,1},{2,3};
    // 2,3: +64), c=col index (0..3: tx*4+c ; 4..7: 64+tx*4+(c-4))
    unsigned long long acc2[4][8];
    #pragma unroll
    for (int i = 0; i < 4; i++)
        #pragma unroll
        for (int j = 0; j < 8; j++) acc2[i][j] = 0ull;

    const unsigned xsA = (unsigned)__cvta_generic_to_shared(&Xs[0][0]) + ty * 16;
    const unsigned xsB = xsA + 64 * 4;
    const unsigned wdA = (unsigned)__cvta_generic_to_shared(&Wd[0][0]) + tx * 32;
    const unsigned wdB = wdA + 128 * 4;

    for (int kt = 0; kt < K; kt += 32) {
        // X tile: 128 rows x 32 k -> transposed into Xs[k][row]
        #pragma unroll
        for (int p = 0; p < 4; p++) {
            int li = tid + p * 256;
            int r  = li >> 3;          // 0..127
            int c4 = li & 7;           // float4 index within 32 k
            int row = row0 + r;
            float4 v = make_float4(0.f, 0.f, 0.f, 0.f);
            if (row < nrows)
                v = *(const float4*)(X + (size_t)row * K + kt + c4 * 4);
            int kk = c4 * 4;
            Xs[kk + 0][r] = v.x;
            Xs[kk + 1][r] = v.y;
            Xs[kk + 2][r] = v.z;
            Xs[kk + 3][r] = v.w;
        }
        // W tile rows kt..kt+31, stored duplicated: Wd[k][2c]=Wd[k][2c+1]=W[k][c]
        #pragma unroll
        for (int p = 0; p < 4; p++) {
            int li = tid + p * 256;
            int k  = li >> 5;          // 0..31
            int c4 = li & 31;          // source float4 col index
            float4 w = *(const float4*)(W + (size_t)(kt + k) * 128 + c4 * 4);
            *(float4*)&Wd[k][c4 * 8]     = make_float4(w.x, w.x, w.y, w.y);
            *(float4*)&Wd[k][c4 * 8 + 4] = make_float4(w.z, w.z, w.w, w.w);
        }
        __syncthreads();

        #pragma unroll
        for (int k = 0; k < 32; k++) {
            unsigned long long x01, x23, x45, x67;   // packed row pairs
            unsigned long long w0, w1, w2, w3, w4, w5, w6, w7;  // dup-packed cols
            asm("ld.shared.v2.b64 {%0,%1}, [%2];"
                : "=l"(x01), "=l"(x23) : "r"(xsA + k * 512));
            asm("ld.shared.v2.b64 {%0,%1}, [%2];"
                : "=l"(x45), "=l"(x67) : "r"(xsB + k * 512));
            asm("ld.shared.v2.b64 {%0,%1}, [%2];"
                : "=l"(w0), "=l"(w1) : "r"(wdA + k * 1024));
            asm("ld.shared.v2.b64 {%0,%1}, [%2];"
                : "=l"(w2), "=l"(w3) : "r"(wdA + k * 1024 + 16));
            asm("ld.shared.v2.b64 {%0,%1}, [%2];"
                : "=l"(w4), "=l"(w5) : "r"(wdB + k * 1024));
            asm("ld.shared.v2.b64 {%0,%1}, [%2];"
                : "=l"(w6), "=l"(w7) : "r"(wdB + k * 1024 + 16));

            FFMA2(acc2[0][0], x01, w0); FFMA2(acc2[0][1], x01, w1);
            FFMA2(acc2[0][2], x01, w2); FFMA2(acc2[0][3], x01, w3);
            FFMA2(acc2[0][4], x01, w4); FFMA2(acc2[0][5], x01, w5);
            FFMA2(acc2[0][6], x01, w6); FFMA2(acc2[0][7], x01, w7);
            FFMA2(acc2[1][0], x23, w0); FFMA2(acc2[1][1], x23, w1);
            FFMA2(acc2[1][2], x23, w2); FFMA2(acc2[1][3], x23, w3);
            FFMA2(acc2[1][4], x23, w4); FFMA2(acc2[1][5], x23, w5);
            FFMA2(acc2[1][6], x23, w6); FFMA2(acc2[1][7], x23, w7);
            FFMA2(acc2[2][0], x45, w0); FFMA2(acc2[2][1], x45, w1);
            FFMA2(acc2[2][2], x45, w2); FFMA2(acc2[2][3], x45, w3);
            FFMA2(acc2[2][4], x45, w4); FFMA2(acc2[2][5], x45, w5);
            FFMA2(acc2[2][6], x45, w6); FFMA2(acc2[2][7], x45, w7);
            FFMA2(acc2[3][0], x67, w0); FFMA2(acc2[3][1], x67, w1);
            FFMA2(acc2[3][2], x67, w2); FFMA2(acc2[3][3], x67, w3);
            FFMA2(acc2[3][4], x67, w4); FFMA2(acc2[3][5], x67, w5);
            FFMA2(acc2[3][6], x67, w6); FFMA2(acc2[3][7], x67, w7);
        }
        __syncthreads();
    }

    float4 bias4[2];
    bias4[0] = *(const float4*)(bias + tx * 4);
    bias4[1] = *(const float4*)(bias + 64 + tx * 4);

    #pragma unroll
    for (int rp = 0; rp < 4; rp++) {
        int rbase = row0 + (rp >> 1) * 64 + ty * 4 + (rp & 1) * 2;
        float lo[8], hi[8];
        #pragma unroll
        for (int c = 0; c < 8; c++)
            asm("mov.b64 {%0,%1}, %2;" : "=f"(lo[c]), "=f"(hi[c]) : "l"(acc2[rp][c]));
        if (rbase < nrows) {
            *(float4*)(Y + (size_t)rbase * 128 + tx * 4) =
                make_float4(lo[0] + bias4[0].x, lo[1] + bias4[0].y,
                            lo[2] + bias4[0].z, lo[3] + bias4[0].w);
            *(float4*)(Y + (size_t)rbase * 128 + 64 + tx * 4) =
                make_float4(lo[4] + bias4[1].x, lo[5] + bias4[1].y,
                            lo[6] + bias4[1].z, lo[7] + bias4[1].w);
        }
        if (rbase + 1 < nrows) {
            *(float4*)(Y + (size_t)(rbase + 1) * 128 + tx * 4) =
                make_float4(hi[0] + bias4[0].x, hi[1] + bias4[0].y,
                            hi[2] + bias4[0].z, hi[3] + bias4[0].w);
            *(float4*)(Y + (size_t)(rbase + 1) * 128 + 64 + tx * 4) =
                make_float4(hi[4] + bias4[1].x, hi[5] + bias4[1].y,
                            hi[6] + bias4[1].z, hi[7] + bias4[1].w);
        }
    }
}

// ---------------- GATv2 edge phase: one warp per destination node ----------------
template<bool FUSE_POOL>
__global__ __launch_bounds__(256) void attn_kernel(
    const float* __restrict__ att, const float* __restrict__ bias,
    const float* __restrict__ Wlin,          // used when FUSE_POOL
    const int* __restrict__ batch)           // used when FUSE_POOL
{
    if (!FUSE_POOL) { (void)Wlin; (void)batch; }

    int w = (blockIdx.x * blockDim.x + threadIdx.x) >> 5;
    int lane = threadIdx.x & 31;
    if (w >= NN) return;

    const float4 xr4  = *(const float4*)(g_xr + (size_t)w * 128 + lane * 4);
    const float4 att4 = *(const float4*)(att + lane * 4);
    int o0 = g_off[w], o1 = g_off[w + 1];

    float m = -3.0e38f, den = 0.f;
    float4 acc = make_float4(0.f, 0.f, 0.f, 0.f);

    // every node has a self loop -> o1 > o0 always
    int src = g_srclist[o0];
    float4 v = *(const float4*)(g_xl + (size_t)src * 128 + lane * 4);

    for (int s = o0; s < o1; s++) {
        float4 vc = v;
        if (s + 1 < o1) {
            int sn = g_srclist[s + 1];
            v = *(const float4*)(g_xl + (size_t)sn * 128 + lane * 4);  // prefetch
        }
        float ex = vc.x + xr4.x, ey = vc.y + xr4.y;
        float ez = vc.z + xr4.z, ew = vc.w + xr4.w;
        ex = (ex > 0.f) ? ex : ex * NEG;
        ey = (ey > 0.f) ? ey : ey * NEG;
        ez = (ez > 0.f) ? ez : ez * NEG;
        ew = (ew > 0.f) ? ew : ew * NEG;
        float pd = fmaf(ex, att4.x, fmaf(ey, att4.y, fmaf(ez, att4.z, ew * att4.w)));
        #pragma unroll
        for (int o = 16; o > 0; o >>= 1)
            pd += __shfl_xor_sync(0xffffffffu, pd, o);

        float nm = fmaxf(m, pd);
        float sc = __expf(m - nm);
        float p  = __expf(pd - nm);
        den = den * sc + p;
        acc.x = fmaf(p, vc.x, acc.x * sc);
        acc.y = fmaf(p, vc.y, acc.y * sc);
        acc.z = fmaf(p, vc.z, acc.z * sc);
        acc.w = fmaf(p, vc.w, acc.w * sc);
        m = nm;
    }

    float inv = 1.f / den;
    float4 b4 = *(const float4*)(bias + lane * 4);
    float4 o4;
    o4.x = fmaxf(fmaf(acc.x, inv, b4.x), 0.f);
    o4.y = fmaxf(fmaf(acc.y, inv, b4.y), 0.f);
    o4.z = fmaxf(fmaf(acc.z, inv, b4.z), 0.f);
    o4.w = fmaxf(fmaf(acc.w, inv, b4.w), 0.f);

    if (!FUSE_POOL) {
        *(float4*)(g_h1 + (size_t)w * 128 + lane * 4) = o4;
    } else {
        float4 wv = *(const float4*)(Wlin + lane * 4);
        float pd = fmaf(o4.x, wv.x, fmaf(o4.y, wv.y, fmaf(o4.z, wv.z, o4.w * wv.w)));
        #pragma unroll
        for (int o = 16; o > 0; o >>= 1)
            pd += __shfl_xor_sync(0xffffffffu, pd, o);
        if (lane == 0) {
            int g = batch[w];
            atomicAdd(&g_sums[g], pd);
            atomicAdd(&g_cnt[g], 1.f);
        }
    }
}

__global__ void final_kernel(const float* __restrict__ blin, float* __restrict__ out) {
    int g = blockIdx.x * blockDim.x + threadIdx.x;
    if (g < GG) out[g] = g_sums[g] / fmaxf(g_cnt[g], 1.f) + blin[0];
}

// ---------------- launch ----------------
extern "C" void kernel_launch(void* const* d_in, const int* in_sizes, int n_in,
                              void* d_out, int out_size) {
    const float* x     = (const float*)d_in[0];
    const int*   ei    = (const int*)d_in[1];     // int32 (JAX x64 disabled)
    const int*   batch = (const int*)d_in[3];     // int32
    const float* Wl1 = (const float*)d_in[4],  *bl1 = (const float*)d_in[5];
    const float* Wr1 = (const float*)d_in[6],  *br1 = (const float*)d_in[7];
    const float* att1= (const float*)d_in[8],  *b1  = (const float*)d_in[9];
    const float* Wl2 = (const float*)d_in[10], *bl2 = (const float*)d_in[11];
    const float* Wr2 = (const float*)d_in[12], *br2 = (const float*)d_in[13];
    const float* att2= (const float*)d_in[14], *b2  = (const float*)d_in[15];
    const float* Wlin= (const float*)d_in[16], *blin= (const float*)d_in[17];
    float* out = (float*)d_out;

    const int edgeBlocks = (ET + 255) / 256;
    const int warpBlocks = (NN * 32 + 255) / 256;   // one warp per node
    dim3 gemmGrid((NN + 127) / 128, 2);

    // CSR build interleaved with layer-1 GEMM (gemm1 is independent of the CSR
    // chain; placing it in the slot ncu profiles gets us real hot-kernel data).
    init_kernel<<<(NN + 255) / 256, 256>>>();
    count_kernel<<<edgeBlocks, 256>>>(ei);
    scan_block_tot<<<NB_SCAN, 256>>>();
    gemm_pair_kernel<FIN, false><<<gemmGrid, 256>>>(x, Wl1, bl1, Wr1, br1, NN);
    scan_block_off<<<1, 256>>>();
    scan_write_off<<<NB_SCAN, 256>>>();
    fill_kernel<<<edgeBlocks, 256>>>(ei);

    // layer 1 attention
    attn_kernel<false><<<warpBlocks, 256>>>(att1, b1, nullptr, nullptr);

    // layer 2: xl/xr <- h1 @ W{l,r}2 + b ; attention fused with pool+head
    gemm_pair_kernel<HH, true><<<gemmGrid, 256>>>(nullptr, Wl2, bl2, Wr2, br2, NN);
    attn_kernel<true><<<warpBlocks, 256>>>(att2, b2, Wlin, batch);

    // head bias + mean division
    final_kernel<<<2, 256>>>(blin, out);
}

// round 15
// speedup vs baseline: 1.4118x; 1.4118x over previous
#include <cuda_runtime.h>
#include <cuda_bf16.h>
#include <math.h>

// Problem constants
#define NN      50000      // nodes
#define EE      800000     // edges (before self loops)
#define ET      850000     // edges + self loops
#define FIN     64
#define HH      128
#define GG      512
#define NEG     0.2f

#define NB_SCAN 196        // ceil(NN/256)
#define XSW     36         // padded X-stage row width (floats)

// ---------------- scratch (device globals; referenced by symbol only) ---------
__device__ __align__(256) float g_xl[NN * HH];
__device__ __align__(256) float g_xr[NN * HH];
__device__ __align__(256) float g_h1[NN * HH];
__device__ int   g_counts[NN];
__device__ int   g_off[NN + 1];
__device__ int   g_cursor[NN];
__device__ int   g_srclist[ET];
__device__ int   g_blockTot[256];
__device__ int   g_blockOff[256];
__device__ float g_sums[GG];
__device__ float g_cnt[GG];

// ---------------- init ----------------
__global__ void init_kernel() {
    int i = blockIdx.x * blockDim.x + threadIdx.x;
    if (i < NN) g_counts[i] = 0;
    if (i < GG) { g_sums[i] = 0.f; g_cnt[i] = 0.f; }
}

// ---------------- CSR build (edge_index/batch are int32) ----------------
__global__ void count_kernel(const int* __restrict__ ei) {
    int i = blockIdx.x * blockDim.x + threadIdx.x;
    if (i >= ET) return;
    int d = (i < EE) ? ei[EE + i] : (i - EE);
    atomicAdd(&g_counts[d], 1);
}

__global__ void scan_block_tot() {
    __shared__ int sm[256];
    int i = blockIdx.x * 256 + threadIdx.x;
    int v = (i < NN) ? g_counts[i] : 0;
    sm[threadIdx.x] = v;
    __syncthreads();
    for (int st = 128; st > 0; st >>= 1) {
        if (threadIdx.x < st) sm[threadIdx.x] += sm[threadIdx.x + st];
        __syncthreads();
    }
    if (threadIdx.x == 0) g_blockTot[blockIdx.x] = sm[0];
}

__global__ void scan_block_off() {
    __shared__ int sm[256];
    int t = threadIdx.x;
    int v = (t < NB_SCAN) ? g_blockTot[t] : 0;
    sm[t] = v;
    __syncthreads();
    for (int st = 1; st < 256; st <<= 1) {
        int a = (t >= st) ? sm[t - st] : 0;
        __syncthreads();
        sm[t] += a;
        __syncthreads();
    }
    if (t < NB_SCAN) g_blockOff[t] = sm[t] - v;   // exclusive
}

__global__ void scan_write_off() {
    __shared__ int sm[256];
    int t = threadIdx.x;
    int i = blockIdx.x * 256 + t;
    int v = (i < NN) ? g_counts[i] : 0;
    sm[t] = v;
    __syncthreads();
    for (int st = 1; st < 256; st <<= 1) {
        int a = (t >= st) ? sm[t - st] : 0;
        __syncthreads();
        sm[t] += a;
        __syncthreads();
    }
    if (i < NN) {
        int ex = g_blockOff[blockIdx.x] + sm[t] - v;
        g_off[i] = ex;
        g_cursor[i] = ex;
    }
    if (i == 0) g_off[NN] = ET;
}

__global__ void fill_kernel(const int* __restrict__ ei) {
    int i = blockIdx.x * blockDim.x + threadIdx.x;
    if (i >= ET) return;
    int s, d;
    if (i < EE) { s = ei[i]; d = ei[EE + i]; }
    else        { s = d = i - EE; }
    int pos = atomicAdd(&g_cursor[d], 1);
    g_srclist[pos] = s;
}

// ---------------- FFMA2 SGEMM pair: {g_xl,g_xr} = X @ W{l,r} + b{l,r} --------
// 128x128 block tile, BK=32, fma.rn.f32x2 (FFMA2, 2x fp32 rate, exact IEEE
// fp32 per lane). Natural smem layouts; k unrolled by 2 with float2-broadcast
// X fetch so the smem crossbar (384 phases/SM/2k) stays under the fma pipe
// (512 cyc/SM/2k) -> fma-bound. acc2 = 64 regs + xp 16; launch_bounds(256,2).
#define FFMA2(acc, a, b) \
    asm("fma.rn.f32x2 %0, %1, %2, %0;" : "+l"(acc) : "l"(a), "l"(b))

template<int K, bool X_FROM_H1>
__global__ __launch_bounds__(256, 2) void gemm_pair_kernel(
    const float* __restrict__ Xin,
    const float* __restrict__ Wl, const float* __restrict__ bl,
    const float* __restrict__ Wr, const float* __restrict__ br,
    int nrows)
{
    __shared__ float Xs[128 * XSW];   // 18.4KB, padded rows (bank-spread)
    __shared__ float Ws[32 * 128];    // 16KB natural

    const float* X    = X_FROM_H1 ? g_h1 : Xin;
    const float* W    = blockIdx.y ? Wr : Wl;
    const float* bias = blockIdx.y ? br : bl;
    float*       Y    = blockIdx.y ? g_xr : g_xl;

    const int tid = threadIdx.x;
    const int tx = tid & 15;          // col group: cols tx*4..+3, 64+tx*4..+3
    const int ty = tid >> 4;          // row group: rows ty*4..+3, 64+ty*4..+3
    const int row0 = blockIdx.x * 128;

    // acc2[i][cp]: i<4 -> row ty*4+i ; i>=4 -> row 64+ty*4+(i-4)
    //              cp<2 -> cols tx*4+2cp,+1 ; cp>=2 -> cols 64+tx*4+2(cp-2),+1
    unsigned long long acc2[8][4];
    #pragma unroll
    for (int i = 0; i < 8; i++)
        #pragma unroll
        for (int j = 0; j < 4; j++) acc2[i][j] = 0ull;

    const unsigned wsBase = (unsigned)__cvta_generic_to_shared(Ws) + tx * 16;

    for (int kt = 0; kt < K; kt += 32) {
        // X tile: 128 rows x 32 k, natural row-major (padded to XSW)
        #pragma unroll
        for (int p = 0; p < 4; p++) {
            int li = tid + p * 256;
            int r  = li >> 3;          // 0..127
            int c4 = li & 7;           // float4 slot
            int row = row0 + r;
            float4 v = make_float4(0.f, 0.f, 0.f, 0.f);
            if (row < nrows)
                v = *(const float4*)(X + (size_t)row * K + kt + c4 * 4);
            *(float4*)&Xs[r * XSW + c4 * 4] = v;
        }
        // W tile: rows kt..kt+31 of W[K][128], direct float4 copy
        #pragma unroll
        for (int p = 0; p < 4; p++) {
            int li = tid + p * 256;
            int k  = li >> 5;          // 0..31
            int c4 = li & 31;
            *(float4*)&Ws[k * 128 + c4 * 4] =
                *(const float4*)(W + (size_t)(kt + k) * 128 + c4 * 4);
        }
        __syncthreads();

        #pragma unroll
        for (int k2 = 0; k2 < 32; k2 += 2) {
            // one float2 broadcast per row covers 2 k-steps
            float2 xp[8];
            #pragma unroll
            for (int i = 0; i < 8; i++) {
                int r = (i < 4) ? (ty * 4 + i) : (64 + ty * 4 + i - 4);
                xp[i] = *(const float2*)&Xs[r * XSW + k2];
            }
            #pragma unroll
            for (int kk = 0; kk < 2; kk++) {
                int k = k2 + kk;
                unsigned long long w01, w23, w45, w67;
                asm("ld.shared.v2.b64 {%0,%1}, [%2];"
                    : "=l"(w01), "=l"(w23) : "r"(wsBase + k * 512));
                asm("ld.shared.v2.b64 {%0,%1}, [%2];"
                    : "=l"(w45), "=l"(w67) : "r"(wsBase + k * 512 + 256));
                #pragma unroll
                for (int i = 0; i < 8; i++) {
                    float xv = kk ? xp[i].y : xp[i].x;
                    unsigned long long xd;
                    asm("mov.b64 %0, {%1,%1};" : "=l"(xd) : "f"(xv));
                    FFMA2(acc2[i][0], xd, w01);
                    FFMA2(acc2[i][1], xd, w23);
                    FFMA2(acc2[i][2], xd, w45);
                    FFMA2(acc2[i][3], xd, w67);
                }
            }
        }
        __syncthreads();
    }

    float4 bias4[2];
    bias4[0] = *(const float4*)(bias + tx * 4);
    bias4[1] = *(const float4*)(bias + 64 + tx * 4);

    #pragma unroll
    for (int i = 0; i < 8; i++) {
        int row = row0 + ((i < 4) ? (ty * 4 + i) : (64 + ty * 4 + i - 4));
        if (row >= nrows) continue;
        float c0l, c0h, c1l, c1h, c2l, c2h, c3l, c3h;
        asm("mov.b64 {%0,%1}, %2;" : "=f"(c0l), "=f"(c0h) : "l"(acc2[i][0]));
        asm("mov.b64 {%0,%1}, %2;" : "=f"(c1l), "=f"(c1h) : "l"(acc2[i][1]));
        asm("mov.b64 {%0,%1}, %2;" : "=f"(c2l), "=f"(c2h) : "l"(acc2[i][2]));
        asm("mov.b64 {%0,%1}, %2;" : "=f"(c3l), "=f"(c3h) : "l"(acc2[i][3]));
        *(float4*)(Y + (size_t)row * 128 + tx * 4) =
            make_float4(c0l + bias4[0].x, c0h + bias4[0].y,
                        c1l + bias4[0].z, c1h + bias4[0].w);
        *(float4*)(Y + (size_t)row * 128 + 64 + tx * 4) =
            make_float4(c2l + bias4[1].x, c2h + bias4[1].y,
                        c3l + bias4[1].z, c3h + bias4[1].w);
    }
}

// ---------------- GATv2 edge phase: one warp per destination node ----------------
template<bool FUSE_POOL>
__global__ __launch_bounds__(256) void attn_kernel(
    const float* __restrict__ att, const float* __restrict__ bias,
    const float* __restrict__ Wlin,          // used when FUSE_POOL
    const int* __restrict__ batch)           // used when FUSE_POOL
{
    if (!FUSE_POOL) { (void)Wlin; (void)batch; }

    int w = (blockIdx.x * blockDim.x + threadIdx.x) >> 5;
    int lane = threadIdx.x & 31;
    if (w >= NN) return;

    const float4 xr4  = *(const float4*)(g_xr + (size_t)w * 128 + lane * 4);
    const float4 att4 = *(const float4*)(att + lane * 4);
    int o0 = g_off[w], o1 = g_off[w + 1];

    float m = -3.0e38f, den = 0.f;
    float4 acc = make_float4(0.f, 0.f, 0.f, 0.f);

    // every node has a self loop -> o1 > o0 always
    int src = g_srclist[o0];
    float4 v = *(const float4*)(g_xl + (size_t)src * 128 + lane * 4);

    for (int s = o0; s < o1; s++) {
        float4 vc = v;
        if (s + 1 < o1) {
            int sn = g_srclist[s + 1];
            v = *(const float4*)(g_xl + (size_t)sn * 128 + lane * 4);  // prefetch
        }
        float ex = vc.x + xr4.x, ey = vc.y + xr4.y;
        float ez = vc.z + xr4.z, ew = vc.w + xr4.w;
        ex = (ex > 0.f) ? ex : ex * NEG;
        ey = (ey > 0.f) ? ey : ey * NEG;
        ez = (ez > 0.f) ? ez : ez * NEG;
        ew = (ew > 0.f) ? ew : ew * NEG;
        float pd = fmaf(ex, att4.x, fmaf(ey, att4.y, fmaf(ez, att4.z, ew * att4.w)));
        #pragma unroll
        for (int o = 16; o > 0; o >>= 1)
            pd += __shfl_xor_sync(0xffffffffu, pd, o);

        float nm = fmaxf(m, pd);
        float sc = __expf(m - nm);
        float p  = __expf(pd - nm);
        den = den * sc + p;
        acc.x = fmaf(p, vc.x, acc.x * sc);
        acc.y = fmaf(p, vc.y, acc.y * sc);
        acc.z = fmaf(p, vc.z, acc.z * sc);
        acc.w = fmaf(p, vc.w, acc.w * sc);
        m = nm;
    }

    float inv = 1.f / den;
    float4 b4 = *(const float4*)(bias + lane * 4);
    float4 o4;
    o4.x = fmaxf(fmaf(acc.x, inv, b4.x), 0.f);
    o4.y = fmaxf(fmaf(acc.y, inv, b4.y), 0.f);
    o4.z = fmaxf(fmaf(acc.z, inv, b4.z), 0.f);
    o4.w = fmaxf(fmaf(acc.w, inv, b4.w), 0.f);

    if (!FUSE_POOL) {
        *(float4*)(g_h1 + (size_t)w * 128 + lane * 4) = o4;
    } else {
        float4 wv = *(const float4*)(Wlin + lane * 4);
        float pd = fmaf(o4.x, wv.x, fmaf(o4.y, wv.y, fmaf(o4.z, wv.z, o4.w * wv.w)));
        #pragma unroll
        for (int o = 16; o > 0; o >>= 1)
            pd += __shfl_xor_sync(0xffffffffu, pd, o);
        if (lane == 0) {
            int g = batch[w];
            atomicAdd(&g_sums[g], pd);
            atomicAdd(&g_cnt[g], 1.f);
        }
    }
}

__global__ void final_kernel(const float* __restrict__ blin, float* __restrict__ out) {
    int g = blockIdx.x * blockDim.x + threadIdx.x;
    if (g < GG) out[g] = g_sums[g] / fmaxf(g_cnt[g], 1.f) + blin[0];
}

// ---------------- launch ----------------
extern "C" void kernel_launch(void* const* d_in, const int* in_sizes, int n_in,
                              void* d_out, int out_size) {
    const float* x     = (const float*)d_in[0];
    const int*   ei    = (const int*)d_in[1];     // int32 (JAX x64 disabled)
    const int*   batch = (const int*)d_in[3];     // int32
    const float* Wl1 = (const float*)d_in[4],  *bl1 = (const float*)d_in[5];
    const float* Wr1 = (const float*)d_in[6],  *br1 = (const float*)d_in[7];
    const float* att1= (const float*)d_in[8],  *b1  = (const float*)d_in[9];
    const float* Wl2 = (const float*)d_in[10], *bl2 = (const float*)d_in[11];
    const float* Wr2 = (const float*)d_in[12], *br2 = (const float*)d_in[13];
    const float* att2= (const float*)d_in[14], *b2  = (const float*)d_in[15];
    const float* Wlin= (const float*)d_in[16], *blin= (const float*)d_in[17];
    float* out = (float*)d_out;

    const int edgeBlocks = (ET + 255) / 256;
    const int warpBlocks = (NN * 32 + 255) / 256;   // one warp per node
    dim3 gemmGrid((NN + 127) / 128, 2);

    // CSR build interleaved with layer-1 GEMM (gemm1 sits in ncu's profiled slot)
    init_kernel<<<(NN + 255) / 256, 256>>>();
    count_kernel<<<edgeBlocks, 256>>>(ei);
    scan_block_tot<<<NB_SCAN, 256>>>();
    gemm_pair_kernel<FIN, false><<<gemmGrid, 256>>>(x, Wl1, bl1, Wr1, br1, NN);
    scan_block_off<<<1, 256>>>();
    scan_write_off<<<NB_SCAN, 256>>>();
    fill_kernel<<<edgeBlocks, 256>>>(ei);

    // layer 1 attention
    attn_kernel<false><<<warpBlocks, 256>>>(att1, b1, nullptr, nullptr);

    // layer 2: xl/xr <- h1 @ W{l,r}2 + b ; attention fused with pool+head
    gemm_pair_kernel<HH, true><<<gemmGrid, 256>>>(nullptr, Wl2, bl2, Wr2, br2, NN);
    attn_kernel<true><<<warpBlocks, 256>>>(att2, b2, Wlin, batch);

    // head bias + mean division
    final_kernel<<<2, 256>>>(blin, out);
}